// round 16
// baseline (speedup 1.0000x reference)
#include <cuda_runtime.h>
#include <math.h>

// ---------------------------------------------------------------------------
// CRF-as-RNN forward — persistent kernel v9, owner-computes + mix-folding.
//  - 96 blocks x 1024 threads; block b owns image row y=b
//  - deg-2 Taylor bilateral feature map (R=21); spatial Gaussian +-12 taps
//  - per iteration: 4 block syncs + 1 grid sync (S4/S6b eliminated:
//    inv-sum folded into mix; moments RED directly to global)
//  - __expf/__fdividef in hot paths; zero-invariants survive graph replays
// ---------------------------------------------------------------------------

typedef unsigned long long ull;

static constexpr int HW   = 96;
static constexpr int NPIX = HW * HW;
static constexpr int NC   = 21;
static constexpr int RD   = 21;             // monomials deg<=2 in 5 vars
static constexpr int GRID = 96;
static constexpr int TPB  = 1024;
static constexpr int NTHR = GRID * TPB;
static constexpr int KR   = 12;
static constexpr int KW   = 2 * KR + 1;     // 25
static constexpr int TROWS = HW + 2 * KR;   // 120
static constexpr int NMOM = NC * RD;        // 441
static constexpr int PHS  = 104;

// smem float offsets
static constexpr int O_MFD  = 0;                    // 441 ull = 882 f
static constexpr int O_PHI  = 884;                  // 21*104 = 2184
static constexpr int O_Q    = 3068;                 // 2016
static constexpr int O_U    = 5084;                 // 2016
static constexpr int O_T1   = 7100;                 // 21*128 (x-padded, +16)
static constexpr int O_T2   = 9788;                 // 2016
static constexpr int O_SP   = 11804;                // 2016
static constexpr int O_BLP  = 13820;                // 3*2016 (also setup scratch)
static constexpr int O_W1D  = 19868;                // 441 ull = 882
static constexpr int O_W2D  = 20750;                // 882
static constexpr int O_CV   = 21632;                // 24
static constexpr int O_KER  = 21656;                // 28
static constexpr int O_GSX  = 21684;                // 96
static constexpr int O_GIX  = 21780;                // 96
static constexpr int O_NBI  = 21876;                // 96
static constexpr int O_IMG  = 21972;                // 864
static constexpr int O_NW   = 22836;                // 568
static constexpr int O_NB   = 23404;                // 28
static constexpr int SMEMF  = 23432;
static constexpr int SMEM_BYTES = SMEMF * 4;        // ~93.7 KB

// ------------------------- device scratch ----------------------------------
// g_tmpP border rows (0..11, 108..119) zero at module load, never written.
__device__ __align__(16) float g_tmpP[NC * TROWS * HW];
__device__ float g_mom[3 * NMOM];           // triple-buffered; zero-invariant
__device__ float g_M0[RD];                  // zero-invariant
__device__ unsigned g_barCount = 0, g_barGen = 0;

__device__ __forceinline__ void gsync() {
    __syncthreads();
    if (threadIdx.x == 0) {
        unsigned* cnt = &g_barCount;
        unsigned* gen = &g_barGen;
        unsigned my;
        asm volatile("ld.relaxed.gpu.u32 %0, [%1];" : "=r"(my) : "l"(gen));
        unsigned prev;
        asm volatile("atom.add.release.gpu.u32 %0, [%1], 1;"
                     : "=r"(prev) : "l"(cnt) : "memory");
        if (prev == GRID - 1u) {
            asm volatile("st.relaxed.gpu.u32 [%0], %1;" :: "l"(cnt), "r"(0u));
            asm volatile("st.release.gpu.u32 [%0], %1;"
                         :: "l"(gen), "r"(my + 1u) : "memory");
        } else {
            unsigned cur;
            do {
                __nanosleep(32);
                asm volatile("ld.acquire.gpu.u32 %0, [%1];"
                             : "=r"(cur) : "l"(gen) : "memory");
            } while (cur == my);
        }
    }
    __syncthreads();
}

__device__ __forceinline__ void fma2(ull& acc, ull a, ull b) {
    asm("fma.rn.f32x2 %0, %1, %2, %0;" : "+l"(acc) : "l"(a), "l"(b));
}
__device__ __forceinline__ ull dup2(float v) {
    unsigned u = __float_as_uint(v);
    return ((ull)u << 32) | (ull)u;
}
__device__ __forceinline__ float lo2(ull a) { return __uint_as_float((unsigned)a); }
__device__ __forceinline__ float hi2(ull a) { return __uint_as_float((unsigned)(a >> 32)); }

__global__ __launch_bounds__(TPB, 1) void crf_all(
    const float* __restrict__ img,
    const float* __restrict__ net_w, const float* __restrict__ net_b,
    const float* __restrict__ sp_w,  const float* __restrict__ sp_b,
    const float* __restrict__ bl_w,  const float* __restrict__ bl_b,
    const float* __restrict__ comp_w,const float* __restrict__ comp_b,
    float* __restrict__ out)
{
    extern __shared__ float sm[];
    ull*   sMfD = (ull*)(sm + O_MFD);
    float* sPhi = sm + O_PHI;
    float* sQ   = sm + O_Q;
    float* sU   = sm + O_U;
    float* sT1  = sm + O_T1;      // stride 128, data at +16
    float* sT2  = sm + O_T2;
    float* sSp  = sm + O_SP;
    float* sBlP = sm + O_BLP;     // 3 partial planes; setup scratch
    ull*   sW1D = (ull*)(sm + O_W1D);
    ull*   sW2D = (ull*)(sm + O_W2D);
    float* sCv  = sm + O_CV;
    float* sKer = sm + O_KER;
    float* sGsx = sm + O_GSX;
    float* sGix = sm + O_GIX;
    float* sNbI = sm + O_NBI;
    float* sImg = sm + O_IMG;
    float* sNw  = sm + O_NW;
    float* sNb  = sm + O_NB;

    const int tid  = threadIdx.x;
    const int y    = blockIdx.x;
    const int gtid = y * TPB + tid;

    // =================== setup a1: raw loads + global zeroing ===============
    for (int t = gtid; t < 2 * NMOM; t += NTHR) g_mom[NMOM + t] = 0.0f;
    for (int t = tid; t < KW; t += TPB) {
        float d = (float)(t - KR) * (1.0f / 3.0f);
        sKer[t] = __expf(-0.5f * d * d);
    }
    for (int t = tid; t < 567; t += TPB) sNw[t] = net_w[t];
    for (int t = tid; t < NC; t += TPB) sNb[t] = net_b[t];
    for (int t = tid; t < 3 * 3 * HW; t += TPB) {
        int c = t / 288, rem = t % 288;
        int ry = rem / 96, x = rem % 96;
        int yy = y + ry - 1;
        sImg[t] = (yy >= 0 && yy < HW) ? img[c * NPIX + yy * HW + x] : 0.0f;
    }
    // stage weight matrices into sBlP scratch
    for (int t = tid; t < NC * NC; t += TPB) {
        sBlP[t] = comp_w[t];
        sBlP[441 + t] = sp_w[t];
        sBlP[882 + t] = bl_w[t];
    }
    for (int t = tid; t < NC; t += TPB) {
        sBlP[1323 + t] = sp_b[t];
        sBlP[1344 + t] = bl_b[t];
        sBlP[1365 + t] = comp_b[t];
    }
    __syncthreads();

    // =================== setup a2: gsx+phi | fold | cv | unary ==============
    if (tid < HW) {
        int px = tid;
        float acc = 0.0f;
        #pragma unroll
        for (int d = 0; d < KW; d++) {
            int xx = px + d - KR;
            if (xx >= 0 && xx < HW) acc += sKer[d];
        }
        sGsx[px] = acc;
        float f0 = ((float)px - 47.5f) * (1.0f / 160.0f);
        float f1 = ((float)y  - 47.5f) * (1.0f / 160.0f);
        float f2 = (sImg[0 * 288 + 96 + px] - 0.5f) * (1.0f / 3.0f);
        float f3 = (sImg[1 * 288 + 96 + px] - 0.5f) * (1.0f / 3.0f);
        float f4 = (sImg[2 * 288 + 96 + px] - 0.5f) * (1.0f / 3.0f);
        float a = __expf(-0.5f * (f0*f0 + f1*f1 + f2*f2 + f3*f3 + f4*f4));
        const float I2 = 0.70710678f;
        int r = 0;
        float v0 = a;
        for (int m0 = 0; m0 <= 2; m0++) {
            float v1 = v0;
            for (int m1 = 0; m1 <= 2 - m0; m1++) {
                float v2 = v1;
                for (int m2 = 0; m2 <= 2 - m0 - m1; m2++) {
                    float v3 = v2;
                    for (int m3 = 0; m3 <= 2 - m0 - m1 - m2; m3++) {
                        float v4 = v3;
                        for (int m4 = 0; m4 <= 2 - m0 - m1 - m2 - m3; m4++) {
                            sPhi[r * PHS + px] = v4;
                            r++;
                            v4 *= f4 * (m4 == 0 ? 1.0f : I2);
                        }
                        v3 *= f3 * (m3 == 0 ? 1.0f : I2);
                    }
                    v2 *= f2 * (m2 == 0 ? 1.0f : I2);
                }
                v1 *= f1 * (m1 == 0 ? 1.0f : I2);
            }
            v0 *= f0 * (m0 == 0 ? 1.0f : I2);
        }
    } else if (tid < 537) {
        int idx = tid - 96;
        int o = idx / NC, k = idx % NC;
        float a1 = 0.0f, a2 = 0.0f;
        #pragma unroll
        for (int c = 0; c < NC; c++) {
            float cw = sBlP[o * NC + c];
            a1 += cw * sBlP[441 + c * NC + k];
            a2 += cw * sBlP[882 + c * NC + k];
        }
        sW1D[idx] = dup2(a1);
        sW2D[idx] = dup2(a2);
    } else if (tid < 558) {
        int t = tid - 537;
        float cv = sBlP[1365 + t];
        #pragma unroll
        for (int c = 0; c < NC; c++)
            cv += sBlP[t * NC + c] * (sBlP[1323 + c] + sBlP[1344 + c]);
        sCv[t] = cv;
    } else {
        for (int t = tid - 558; t < NC * HW; t += TPB - 558) {
            int o = t / HW, x = t % HW;
            float acc = sNb[o];
            #pragma unroll
            for (int c = 0; c < 3; c++)
                #pragma unroll
                for (int ky = 0; ky < 3; ky++)
                    #pragma unroll
                    for (int kx = 0; kx < 3; kx++) {
                        int xx = x + kx - 1;
                        if (xx < 0 || xx >= HW) continue;
                        acc += sImg[c * 288 + ky * 96 + xx]
                             * sNw[((o * 3 + c) * 3 + ky) * 3 + kx];
                    }
            sU[t] = acc;
        }
    }
    __syncthreads();

    // ====== setup c: gix | exp(u) | M0 RED | zero sT1 pads ==================
    if (tid < HW) {
        sGix[tid] = __fdividef(1.0f, sGsx[y] * sGsx[tid]);
    } else if (tid < 768) {
        for (int u2 = tid - 96; u2 < NC * HW; u2 += 672) sQ[u2] = __expf(sU[u2]);
    } else if (tid < 768 + RD) {
        int r = tid - 768;
        float acc = 0.0f;
        for (int px = 0; px < HW; px++) acc += sPhi[r * PHS + px];
        atomicAdd(&g_M0[r], acc);            // zeroed by prev launch (it==2)
    } else if (tid >= 800) {
        for (int i = tid - 800; i < NC * 32; i += 224) {
            int c = i / 32, j = i % 32;
            sT1[c * 128 + (j < 16 ? j : 96 + j)] = 0.0f;
        }
    }
    __syncthreads();

    // ====== setup e: mix t1=W1·s, t2=W2·s (inv-sum folded in) ===============
    if (tid < 336) {
        int og = tid / 48, pp = tid % 48;
        int o0 = og * 3;
        const ull ONE = dup2(1.0f);
        ull t1a[3] = {0, 0, 0}, t2a[3] = {0, 0, 0}, ssum = 0ull;
        #pragma unroll
        for (int c = 0; c < NC; c++) {
            ull sv = *(const ull*)(sQ + c * 96 + 2 * pp);
            fma2(ssum, sv, ONE);
            #pragma unroll
            for (int k = 0; k < 3; k++) {
                fma2(t1a[k], sv, sW1D[(o0 + k) * NC + c]);
                fma2(t2a[k], sv, sW2D[(o0 + k) * NC + c]);
            }
        }
        float i0 = __fdividef(1.0f, lo2(ssum));
        float i1 = __fdividef(1.0f, hi2(ssum));
        #pragma unroll
        for (int k = 0; k < 3; k++) {
            sT1[(o0 + k) * 128 + 16 + 2 * pp]     = lo2(t1a[k]) * i0;
            sT1[(o0 + k) * 128 + 16 + 2 * pp + 1] = hi2(t1a[k]) * i1;
            sT2[(o0 + k) * 96 + 2 * pp]           = lo2(t2a[k]) * i0;
            sT2[(o0 + k) * 96 + 2 * pp + 1]       = hi2(t2a[k]) * i1;
        }
    }
    __syncthreads();

    // ====== setup f: spX(t1) | moments(t2) -> RED buf0 ======================
    if (tid < 504) {
        int c = tid / 24, q4 = tid % 24;
        float w[28];
        const float* base = sT1 + c * 128 + 4 + 4 * q4;
        #pragma unroll
        for (int i = 0; i < 7; i++) *(float4*)(w + 4 * i) = *(const float4*)(base + 4 * i);
        float a0 = 0.f, a1 = 0.f, a2 = 0.f, a3 = 0.f;
        #pragma unroll
        for (int d = 0; d < KW; d++) {
            float k = sKer[d];
            a0 += k * w[d]; a1 += k * w[d + 1]; a2 += k * w[d + 2]; a3 += k * w[d + 3];
        }
        *(float4*)(g_tmpP + (c * TROWS + KR + y) * HW + 4 * q4) = make_float4(a0, a1, a2, a3);
    } else if (tid >= 512 && tid < 708) {
        int u2 = tid - 512;
        int quarter = u2 / 49, r2 = u2 % 49;
        int cg = r2 / 7, rg = r2 % 7;
        int r0 = rg * 3, c0 = cg * 3;
        ull acc[9];
        #pragma unroll
        for (int k = 0; k < 9; k++) acc[k] = 0ull;
        int p0 = quarter * 12;
        for (int p = p0; p < p0 + 12; p++) {
            ull ph0 = *(const ull*)(sPhi + (r0 + 0) * PHS + 2 * p);
            ull ph1 = *(const ull*)(sPhi + (r0 + 1) * PHS + 2 * p);
            ull ph2 = *(const ull*)(sPhi + (r0 + 2) * PHS + 2 * p);
            #pragma unroll
            for (int j = 0; j < 3; j++) {
                ull sv = *(const ull*)(sT2 + (c0 + j) * 96 + 2 * p);
                fma2(acc[j * 3 + 0], ph0, sv);
                fma2(acc[j * 3 + 1], ph1, sv);
                fma2(acc[j * 3 + 2], ph2, sv);
            }
        }
        #pragma unroll
        for (int j = 0; j < 3; j++)
            #pragma unroll
            for (int i = 0; i < 3; i++)
                atomicAdd(&g_mom[(c0 + j) * RD + r0 + i],
                          lo2(acc[j * 3 + i]) + hi2(acc[j * 3 + i]));
    }
    gsync();                                 // barrier #1

    // ======================= mean-field iterations ==========================
    for (int it = 0; it < 5; it++) {
        const int rdb = it % 3, zrb = (it + 2) % 3;
        const int wrb = (it + 1) % 3;

        // ---- A: spY (0..503) | mom dup-load + zero future (512..952) -------
        if (tid < 504) {
            int c = tid / 24, q4 = tid % 24;
            float4 a = make_float4(0.f, 0.f, 0.f, 0.f);
            const float* base = g_tmpP + (c * TROWS + y) * HW + 4 * q4;
            #pragma unroll
            for (int d = 0; d < KW; d++) {
                float4 tv = *(const float4*)(base + d * HW);
                float k = sKer[d];
                a.x += tv.x * k; a.y += tv.y * k;
                a.z += tv.z * k; a.w += tv.w * k;
            }
            int px = 4 * q4;
            sSp[c * 96 + px + 0] = a.x * sGix[px + 0];
            sSp[c * 96 + px + 1] = a.y * sGix[px + 1];
            sSp[c * 96 + px + 2] = a.z * sGix[px + 2];
            sSp[c * 96 + px + 3] = a.w * sGix[px + 3];
        } else if (tid >= 512 && tid < 512 + NMOM) {
            int t = tid - 512;
            sMfD[t] = dup2(g_mom[rdb * NMOM + t]);
            g_mom[zrb * NMOM + t] = 0.0f;
        }
        __syncthreads();

        // ---- B: bl partials (0..503) | [it0: nbI] | [it2: M0 zero] ---------
        if (tid < 504) {
            int rh = tid / 168, u2 = tid % 168;
            int cg = u2 / 24, q4 = u2 % 24;
            int c0 = cg * 3;
            ull a[6];
            #pragma unroll
            for (int k = 0; k < 6; k++) a[k] = 0ull;
            int rbase = rh * 7;
            #pragma unroll
            for (int rr = 0; rr < 7; rr++) {
                int r = rbase + rr;
                ulonglong2 ph = *(const ulonglong2*)(sPhi + r * PHS + 4 * q4);
                #pragma unroll
                for (int k = 0; k < 3; k++) {
                    ull m = sMfD[(c0 + k) * RD + r];
                    fma2(a[2 * k], ph.x, m);
                    fma2(a[2 * k + 1], ph.y, m);
                }
            }
            float* dst = sBlP + rh * 2016;
            #pragma unroll
            for (int k = 0; k < 3; k++) {
                dst[(c0 + k) * 96 + 4 * q4 + 0] = lo2(a[2 * k]);
                dst[(c0 + k) * 96 + 4 * q4 + 1] = hi2(a[2 * k]);
                dst[(c0 + k) * 96 + 4 * q4 + 2] = lo2(a[2 * k + 1]);
                dst[(c0 + k) * 96 + 4 * q4 + 3] = hi2(a[2 * k + 1]);
            }
        } else if (it == 0 && tid >= 512 && tid < 608) {
            int px = tid - 512;
            float acc = 0.0f;
            #pragma unroll
            for (int r = 0; r < RD; r++) acc += sPhi[r * PHS + px] * g_M0[r];
            sNbI[px] = __fdividef(1.0f, acc);
        } else if (it == 2 && tid >= 608 && tid < 608 + RD) {
            g_M0[tid - 608] = 0.0f;
        }
        __syncthreads();

        // ---- S3: q = u - cvec - sp - bl; exp -------------------------------
        if (tid < 672) {
            #pragma unroll
            for (int j = 0; j < 3; j++) {
                int idx = tid + j * 672;
                int o = idx / 96, px = idx % 96;
                float bl = (sBlP[idx] + sBlP[2016 + idx] + sBlP[4032 + idx]) * sNbI[px];
                float q = sU[idx] - sCv[o] - sSp[idx] - bl;
                sQ[idx] = __expf(q);
            }
        }
        __syncthreads();

        // ---- final iteration: normalize + output, done ---------------------
        if (it == 4) {
            if (tid < HW) {
                int px = tid;
                float ss = 0.0f;
                #pragma unroll
                for (int o = 0; o < NC; o++) ss += sQ[o * 96 + px];
                float inv = __fdividef(1.0f, ss);
                #pragma unroll
                for (int o = 0; o < NC; o++)
                    out[o * NPIX + y * HW + px] = sQ[o * 96 + px] * inv;
            }
            break;
        }

        // ---- S5: mix t1, t2 (inv-sum folded in) ----------------------------
        if (tid < 336) {
            int og = tid / 48, pp = tid % 48;
            int o0 = og * 3;
            const ull ONE = dup2(1.0f);
            ull t1a[3] = {0, 0, 0}, t2a[3] = {0, 0, 0}, ssum = 0ull;
            #pragma unroll
            for (int c = 0; c < NC; c++) {
                ull sv = *(const ull*)(sQ + c * 96 + 2 * pp);
                fma2(ssum, sv, ONE);
                #pragma unroll
                for (int k = 0; k < 3; k++) {
                    fma2(t1a[k], sv, sW1D[(o0 + k) * NC + c]);
                    fma2(t2a[k], sv, sW2D[(o0 + k) * NC + c]);
                }
            }
            float i0 = __fdividef(1.0f, lo2(ssum));
            float i1 = __fdividef(1.0f, hi2(ssum));
            #pragma unroll
            for (int k = 0; k < 3; k++) {
                sT1[(o0 + k) * 128 + 16 + 2 * pp]     = lo2(t1a[k]) * i0;
                sT1[(o0 + k) * 128 + 16 + 2 * pp + 1] = hi2(t1a[k]) * i1;
                sT2[(o0 + k) * 96 + 2 * pp]           = lo2(t2a[k]) * i0;
                sT2[(o0 + k) * 96 + 2 * pp + 1]       = hi2(t2a[k]) * i1;
            }
        }
        __syncthreads();

        // ---- S6: spX(t1) | moments(t2) -> RED mom[wrb] ---------------------
        if (tid < 504) {
            int c = tid / 24, q4 = tid % 24;
            float w[28];
            const float* base = sT1 + c * 128 + 4 + 4 * q4;
            #pragma unroll
            for (int i = 0; i < 7; i++) *(float4*)(w + 4 * i) = *(const float4*)(base + 4 * i);
            float a0 = 0.f, a1 = 0.f, a2 = 0.f, a3 = 0.f;
            #pragma unroll
            for (int d = 0; d < KW; d++) {
                float k = sKer[d];
                a0 += k * w[d]; a1 += k * w[d + 1]; a2 += k * w[d + 2]; a3 += k * w[d + 3];
            }
            *(float4*)(g_tmpP + (c * TROWS + KR + y) * HW + 4 * q4) = make_float4(a0, a1, a2, a3);
        } else if (tid >= 512 && tid < 708) {
            int u2 = tid - 512;
            int quarter = u2 / 49, r2 = u2 % 49;
            int cg = r2 / 7, rg = r2 % 7;
            int r0 = rg * 3, c0 = cg * 3;
            ull acc[9];
            #pragma unroll
            for (int k = 0; k < 9; k++) acc[k] = 0ull;
            int p0 = quarter * 12;
            for (int p = p0; p < p0 + 12; p++) {
                ull ph0 = *(const ull*)(sPhi + (r0 + 0) * PHS + 2 * p);
                ull ph1 = *(const ull*)(sPhi + (r0 + 1) * PHS + 2 * p);
                ull ph2 = *(const ull*)(sPhi + (r0 + 2) * PHS + 2 * p);
                #pragma unroll
                for (int j = 0; j < 3; j++) {
                    ull sv = *(const ull*)(sT2 + (c0 + j) * 96 + 2 * p);
                    fma2(acc[j * 3 + 0], ph0, sv);
                    fma2(acc[j * 3 + 1], ph1, sv);
                    fma2(acc[j * 3 + 2], ph2, sv);
                }
            }
            #pragma unroll
            for (int j = 0; j < 3; j++)
                #pragma unroll
                for (int i = 0; i < 3; i++)
                    atomicAdd(&g_mom[wrb * NMOM + (c0 + j) * RD + r0 + i],
                              lo2(acc[j * 3 + i]) + hi2(acc[j * 3 + i]));
        }
        gsync();                             // barriers #2..#5
    }
}

// ------------------------------ launch -------------------------------------
extern "C" void kernel_launch(void* const* d_in, const int* in_sizes, int n_in,
                              void* d_out, int out_size) {
    const float* image  = (const float*)d_in[0];
    const float* net_w  = (const float*)d_in[1];
    const float* net_b  = (const float*)d_in[2];
    const float* sp_w   = (const float*)d_in[3];
    const float* sp_b   = (const float*)d_in[4];
    const float* bl_w   = (const float*)d_in[5];
    const float* bl_b   = (const float*)d_in[6];
    const float* comp_w = (const float*)d_in[7];
    const float* comp_b = (const float*)d_in[8];
    float* out = (float*)d_out;

    static int smem_set = 0;
    if (!smem_set) {
        cudaFuncSetAttribute(crf_all, cudaFuncAttributeMaxDynamicSharedMemorySize,
                             SMEM_BYTES);
        smem_set = 1;
    }
    crf_all<<<GRID, TPB, SMEM_BYTES>>>(image, net_w, net_b, sp_w, sp_b,
                                       bl_w, bl_b, comp_w, comp_b, out);
}

// round 17
// speedup vs baseline: 2.0423x; 2.0423x over previous
#include <cuda_runtime.h>
#include <math.h>

// ---------------------------------------------------------------------------
// CRF-as-RNN forward — persistent kernel v10 = v8 structure (best known)
//   + __expf/__fdividef + smem-staged weight folding. NO structural changes:
//   v9's stage re-pairing serialized bl after spY and regressed 2x.
//  - 96 blocks x 1024 threads; block b owns image row y=b
//  - deg-2 Taylor bilateral feature map (R=21); spatial Gaussian +-12 taps
//  - 5 grid barriers; zero-invariants survive graph replays
// ---------------------------------------------------------------------------

typedef unsigned long long ull;

static constexpr int HW   = 96;
static constexpr int NPIX = HW * HW;
static constexpr int NC   = 21;
static constexpr int RD   = 21;             // monomials deg<=2 in 5 vars
static constexpr int GRID = 96;
static constexpr int TPB  = 1024;
static constexpr int NTHR = GRID * TPB;
static constexpr int KR   = 12;
static constexpr int KW   = 2 * KR + 1;     // 25
static constexpr int TROWS = HW + 2 * KR;   // 120
static constexpr int NMOM = NC * RD;        // 441
static constexpr int PHS  = 104;

// smem float offsets (all multiples of 4)
static constexpr int O_MFD  = 0;                    // 441 ull = 882 f
static constexpr int O_MOMP = 884;                  // 4*441 = 1764 (also setup scratch)
static constexpr int O_PHI  = 2648;                 // 21*104 = 2184
static constexpr int O_Q    = 4832;                 // 2016
static constexpr int O_U    = 6848;                 // 2016
static constexpr int O_T1   = 8864;                 // 21*128 (x-padded, +16)
static constexpr int O_T2   = 11552;                // 2016
static constexpr int O_SP   = 13568;                // 2016
static constexpr int O_BLP  = 15584;                // 3*2016 = 6048
static constexpr int O_W1D  = 21632;                // 441 ull = 882
static constexpr int O_W2D  = 22516;                // 882
static constexpr int O_CV   = 23400;                // 24
static constexpr int O_KER  = 23424;                // 28
static constexpr int O_GSX  = 23452;                // 96
static constexpr int O_GIX  = 23548;                // 96
static constexpr int O_NBI  = 23644;                // 96
static constexpr int O_IV   = 23740;                // 96
static constexpr int O_IMG  = 23836;                // 864
static constexpr int O_NW   = 24700;                // 568
static constexpr int O_NB   = 25268;                // 28
static constexpr int SMEMF  = 25296;
static constexpr int SMEM_BYTES = SMEMF * 4;        // ~98.8 KB

// ------------------------- device scratch ----------------------------------
// g_tmpP border rows (0..11, 108..119) zero at module load, never written.
__device__ __align__(16) float g_tmpP[NC * TROWS * HW];
__device__ float g_mom[3 * NMOM];           // triple-buffered; zero-invariant
__device__ float g_M0[RD];                  // zero-invariant
__device__ unsigned g_barCount = 0, g_barGen = 0;

__device__ __forceinline__ void gsync() {
    __syncthreads();
    if (threadIdx.x == 0) {
        unsigned* cnt = &g_barCount;
        unsigned* gen = &g_barGen;
        unsigned my;
        asm volatile("ld.relaxed.gpu.u32 %0, [%1];" : "=r"(my) : "l"(gen));
        unsigned prev;
        asm volatile("atom.add.release.gpu.u32 %0, [%1], 1;"
                     : "=r"(prev) : "l"(cnt) : "memory");
        if (prev == GRID - 1u) {
            asm volatile("st.relaxed.gpu.u32 [%0], %1;" :: "l"(cnt), "r"(0u));
            asm volatile("st.release.gpu.u32 [%0], %1;"
                         :: "l"(gen), "r"(my + 1u) : "memory");
        } else {
            unsigned cur;
            do {
                __nanosleep(32);
                asm volatile("ld.acquire.gpu.u32 %0, [%1];"
                             : "=r"(cur) : "l"(gen) : "memory");
            } while (cur == my);
        }
    }
    __syncthreads();
}

__device__ __forceinline__ void fma2(ull& acc, ull a, ull b) {
    asm("fma.rn.f32x2 %0, %1, %2, %0;" : "+l"(acc) : "l"(a), "l"(b));
}
__device__ __forceinline__ ull dup2(float v) {
    unsigned u = __float_as_uint(v);
    return ((ull)u << 32) | (ull)u;
}
__device__ __forceinline__ float lo2(ull a) { return __uint_as_float((unsigned)a); }
__device__ __forceinline__ float hi2(ull a) { return __uint_as_float((unsigned)(a >> 32)); }

__global__ __launch_bounds__(TPB, 1) void crf_all(
    const float* __restrict__ img,
    const float* __restrict__ net_w, const float* __restrict__ net_b,
    const float* __restrict__ sp_w,  const float* __restrict__ sp_b,
    const float* __restrict__ bl_w,  const float* __restrict__ bl_b,
    const float* __restrict__ comp_w,const float* __restrict__ comp_b,
    float* __restrict__ out)
{
    extern __shared__ float sm[];
    ull*   sMfD = (ull*)(sm + O_MFD);
    float* sMomP= sm + O_MOMP;    // moments partials; setup weight scratch
    float* sPhi = sm + O_PHI;
    float* sQ   = sm + O_Q;
    float* sU   = sm + O_U;
    float* sT1  = sm + O_T1;      // stride 128, data at +16
    float* sT2  = sm + O_T2;
    float* sSp  = sm + O_SP;
    float* sBlP = sm + O_BLP;     // three 2016-float partial planes
    ull*   sW1D = (ull*)(sm + O_W1D);
    ull*   sW2D = (ull*)(sm + O_W2D);
    float* sCv  = sm + O_CV;
    float* sKer = sm + O_KER;
    float* sGsx = sm + O_GSX;
    float* sGix = sm + O_GIX;
    float* sNbI = sm + O_NBI;
    float* sIv  = sm + O_IV;
    float* sImg = sm + O_IMG;
    float* sNw  = sm + O_NW;
    float* sNb  = sm + O_NB;

    const int tid  = threadIdx.x;
    const int y    = blockIdx.x;
    const int gtid = y * TPB + tid;

    // =================== setup (a): loads + global zeroing ==================
    for (int t = gtid; t < 2 * NMOM; t += NTHR) g_mom[NMOM + t] = 0.0f;
    for (int t = tid; t < KW; t += TPB) {
        float d = (float)(t - KR) * (1.0f / 3.0f);
        sKer[t] = __expf(-0.5f * d * d);
    }
    for (int t = tid; t < 567; t += TPB) sNw[t] = net_w[t];
    for (int t = tid; t < NC; t += TPB) sNb[t] = net_b[t];
    for (int t = tid; t < 3 * 3 * HW; t += TPB) {
        int c = t / 288, rem = t % 288;
        int ry = rem / 96, x = rem % 96;
        int yy = y + ry - 1;
        sImg[t] = (yy >= 0 && yy < HW) ? img[c * NPIX + yy * HW + x] : 0.0f;
    }
    // stage raw weight matrices into sMomP scratch (1386 <= 1764 floats)
    for (int t = tid; t < NC * NC; t += TPB) {
        sMomP[t] = comp_w[t];
        sMomP[441 + t] = sp_w[t];
        sMomP[882 + t] = bl_w[t];
    }
    for (int t = tid; t < NC; t += TPB) {
        sMomP[1323 + t] = sp_b[t];
        sMomP[1344 + t] = bl_b[t];
        sMomP[1365 + t] = comp_b[t];
    }
    __syncthreads();

    // ========= setup (b): gsx+phi (deg-2) | W-fold | cv | unary =============
    if (tid < HW) {
        int px = tid;
        float acc = 0.0f;
        #pragma unroll
        for (int d = 0; d < KW; d++) {
            int xx = px + d - KR;
            if (xx >= 0 && xx < HW) acc += sKer[d];
        }
        sGsx[px] = acc;
        float f0 = ((float)px - 47.5f) * (1.0f / 160.0f);
        float f1 = ((float)y  - 47.5f) * (1.0f / 160.0f);
        float f2 = (sImg[0 * 288 + 96 + px] - 0.5f) * (1.0f / 3.0f);
        float f3 = (sImg[1 * 288 + 96 + px] - 0.5f) * (1.0f / 3.0f);
        float f4 = (sImg[2 * 288 + 96 + px] - 0.5f) * (1.0f / 3.0f);
        float a = __expf(-0.5f * (f0*f0 + f1*f1 + f2*f2 + f3*f3 + f4*f4));
        const float I2 = 0.70710678f;
        int r = 0;
        float v0 = a;
        for (int m0 = 0; m0 <= 2; m0++) {
            float v1 = v0;
            for (int m1 = 0; m1 <= 2 - m0; m1++) {
                float v2 = v1;
                for (int m2 = 0; m2 <= 2 - m0 - m1; m2++) {
                    float v3 = v2;
                    for (int m3 = 0; m3 <= 2 - m0 - m1 - m2; m3++) {
                        float v4 = v3;
                        for (int m4 = 0; m4 <= 2 - m0 - m1 - m2 - m3; m4++) {
                            sPhi[r * PHS + px] = v4;
                            r++;
                            v4 *= f4 * (m4 == 0 ? 1.0f : I2);
                        }
                        v3 *= f3 * (m3 == 0 ? 1.0f : I2);
                    }
                    v2 *= f2 * (m2 == 0 ? 1.0f : I2);
                }
                v1 *= f1 * (m1 == 0 ? 1.0f : I2);
            }
            v0 *= f0 * (m0 == 0 ? 1.0f : I2);
        }
    } else if (tid < 537) {
        int idx = tid - 96;
        int o = idx / NC, k = idx % NC;
        float a1 = 0.0f, a2 = 0.0f;
        #pragma unroll
        for (int c = 0; c < NC; c++) {
            float cw = sMomP[o * NC + c];
            a1 += cw * sMomP[441 + c * NC + k];
            a2 += cw * sMomP[882 + c * NC + k];
        }
        sW1D[idx] = dup2(a1);
        sW2D[idx] = dup2(a2);
    } else if (tid < 558) {
        int t = tid - 537;
        float cv = sMomP[1365 + t];
        #pragma unroll
        for (int c = 0; c < NC; c++)
            cv += sMomP[t * NC + c] * (sMomP[1323 + c] + sMomP[1344 + c]);
        sCv[t] = cv;
    } else {
        for (int t = tid - 558; t < NC * HW; t += TPB - 558) {
            int o = t / HW, x = t % HW;
            float acc = sNb[o];
            #pragma unroll
            for (int c = 0; c < 3; c++)
                #pragma unroll
                for (int ky = 0; ky < 3; ky++)
                    #pragma unroll
                    for (int kx = 0; kx < 3; kx++) {
                        int xx = x + kx - 1;
                        if (xx < 0 || xx >= HW) continue;
                        acc += sImg[c * 288 + ky * 96 + xx]
                             * sNw[((o * 3 + c) * 3 + ky) * 3 + kx];
                    }
            sU[t] = acc;
        }
    }
    __syncthreads();

    // ====== setup (c): gix | exp(u) | M0 atomics | zero sT1 pads ============
    if (tid < HW) {
        sGix[tid] = __fdividef(1.0f, sGsx[y] * sGsx[tid]);
    } else if (tid < 768) {
        for (int u2 = tid - 96; u2 < NC * HW; u2 += 672) sQ[u2] = __expf(sU[u2]);
    } else if (tid < 768 + RD) {
        int r = tid - 768;
        float acc = 0.0f;
        for (int px = 0; px < HW; px++) acc += sPhi[r * PHS + px];
        atomicAdd(&g_M0[r], acc);            // zeroed by prev launch (it==2)
    } else if (tid >= 824) {
        for (int i = tid - 824; i < NC * 32; i += 200) {
            int c = i / 32, j = i % 32;
            sT1[c * 128 + (j < 16 ? j : 96 + j)] = 0.0f;
        }
    }
    __syncthreads();

    // ====== setup (d): inv-sum =============================================
    if (tid < HW) {
        int px = tid;
        float ss = 0.0f;
        #pragma unroll
        for (int o = 0; o < NC; o++) ss += sQ[o * 96 + px];
        sIv[px] = __fdividef(1.0f, ss);
    }
    __syncthreads();

    // ====== setup (e): mix t1=W1·s, t2=W2·s ================================
    if (tid < 336) {
        int og = tid / 48, pp = tid % 48;
        int o0 = og * 3;
        ull t1a[3] = {0, 0, 0}, t2a[3] = {0, 0, 0};
        for (int c = 0; c < NC; c++) {
            ull sv = *(const ull*)(sQ + c * 96 + 2 * pp);
            #pragma unroll
            for (int k = 0; k < 3; k++) {
                fma2(t1a[k], sv, sW1D[(o0 + k) * NC + c]);
                fma2(t2a[k], sv, sW2D[(o0 + k) * NC + c]);
            }
        }
        float i0 = sIv[2 * pp], i1 = sIv[2 * pp + 1];
        #pragma unroll
        for (int k = 0; k < 3; k++) {
            sT1[(o0 + k) * 128 + 16 + 2 * pp]     = lo2(t1a[k]) * i0;
            sT1[(o0 + k) * 128 + 16 + 2 * pp + 1] = hi2(t1a[k]) * i1;
            sT2[(o0 + k) * 96 + 2 * pp]           = lo2(t2a[k]) * i0;
            sT2[(o0 + k) * 96 + 2 * pp + 1]       = hi2(t2a[k]) * i1;
        }
    }
    __syncthreads();

    // ====== setup (f): spX(t1) | moments(t2) ===============================
    if (tid < 504) {
        int c = tid / 24, q4 = tid % 24;
        float w[28];
        const float* base = sT1 + c * 128 + 4 + 4 * q4;
        #pragma unroll
        for (int i = 0; i < 7; i++) *(float4*)(w + 4 * i) = *(const float4*)(base + 4 * i);
        float a0 = 0.f, a1 = 0.f, a2 = 0.f, a3 = 0.f;
        #pragma unroll
        for (int d = 0; d < KW; d++) {
            float k = sKer[d];
            a0 += k * w[d]; a1 += k * w[d + 1]; a2 += k * w[d + 2]; a3 += k * w[d + 3];
        }
        *(float4*)(g_tmpP + (c * TROWS + KR + y) * HW + 4 * q4) = make_float4(a0, a1, a2, a3);
    } else if (tid >= 512 && tid < 708) {
        int u2 = tid - 512;
        int quarter = u2 / 49, r2 = u2 % 49;
        int cg = r2 / 7, rg = r2 % 7;
        int r0 = rg * 3, c0 = cg * 3;
        ull acc[9];
        #pragma unroll
        for (int k = 0; k < 9; k++) acc[k] = 0ull;
        int p0 = quarter * 12;
        for (int p = p0; p < p0 + 12; p++) {
            ull ph0 = *(const ull*)(sPhi + (r0 + 0) * PHS + 2 * p);
            ull ph1 = *(const ull*)(sPhi + (r0 + 1) * PHS + 2 * p);
            ull ph2 = *(const ull*)(sPhi + (r0 + 2) * PHS + 2 * p);
            #pragma unroll
            for (int j = 0; j < 3; j++) {
                ull sv = *(const ull*)(sT2 + (c0 + j) * 96 + 2 * p);
                fma2(acc[j * 3 + 0], ph0, sv);
                fma2(acc[j * 3 + 1], ph1, sv);
                fma2(acc[j * 3 + 2], ph2, sv);
            }
        }
        #pragma unroll
        for (int j = 0; j < 3; j++)
            #pragma unroll
            for (int i = 0; i < 3; i++)
                sMomP[quarter * NMOM + (c0 + j) * RD + r0 + i] =
                    lo2(acc[j * 3 + i]) + hi2(acc[j * 3 + i]);
    }
    __syncthreads();
    // setup (g): reduce -> mom buffer 0 (zeroed by prev launch at it4)
    if (tid < NMOM) {
        float v = sMomP[tid] + sMomP[NMOM + tid]
                + sMomP[2 * NMOM + tid] + sMomP[3 * NMOM + tid];
        atomicAdd(&g_mom[tid], v);
    }
    gsync();                                 // barrier #1

    // ======================= mean-field iterations ==========================
    for (int it = 0; it < 5; it++) {
        const int rdb = it % 3, wrb = (it + 1) % 3, zrb = (it + 2) % 3;

        // ---- S1: dup-load moments | zero future buffer | [it0: nbI] --------
        if (tid < NMOM) {
            sMfD[tid] = dup2(g_mom[rdb * NMOM + tid]);
        } else if (tid < 2 * NMOM) {
            g_mom[zrb * NMOM + (tid - NMOM)] = 0.0f;
        } else if (it == 2 && tid >= 882 && tid < 882 + RD) {
            g_M0[tid - 882] = 0.0f;
        }
        if (it == 0 && tid >= 896 && tid < 896 + HW) {
            int px = tid - 896;
            float acc = 0.0f;
            for (int r = 0; r < RD; r++) acc += sPhi[r * PHS + px] * g_M0[r];
            sNbI[px] = __fdividef(1.0f, acc);
        }
        __syncthreads();

        // ---- S2: bl partials (0..503) | spY (512..1015) --------------------
        if (tid < 504) {
            int rh = tid / 168, u2 = tid % 168;
            int cg = u2 / 24, q4 = u2 % 24;
            int c0 = cg * 3;
            ull a[6];
            #pragma unroll
            for (int k = 0; k < 6; k++) a[k] = 0ull;
            int rbase = rh * 7;
            #pragma unroll
            for (int rr = 0; rr < 7; rr++) {
                int r = rbase + rr;
                ulonglong2 ph = *(const ulonglong2*)(sPhi + r * PHS + 4 * q4);
                #pragma unroll
                for (int k = 0; k < 3; k++) {
                    ull m = sMfD[(c0 + k) * RD + r];
                    fma2(a[2 * k], ph.x, m);
                    fma2(a[2 * k + 1], ph.y, m);
                }
            }
            float* dst = sBlP + rh * 2016;
            #pragma unroll
            for (int k = 0; k < 3; k++) {
                dst[(c0 + k) * 96 + 4 * q4 + 0] = lo2(a[2 * k]);
                dst[(c0 + k) * 96 + 4 * q4 + 1] = hi2(a[2 * k]);
                dst[(c0 + k) * 96 + 4 * q4 + 2] = lo2(a[2 * k + 1]);
                dst[(c0 + k) * 96 + 4 * q4 + 3] = hi2(a[2 * k + 1]);
            }
        } else if (tid >= 512 && tid < 1016) {
            int u2 = tid - 512;
            int c = u2 / 24, q4 = u2 % 24;
            float4 a = make_float4(0.f, 0.f, 0.f, 0.f);
            const float* base = g_tmpP + (c * TROWS + y) * HW + 4 * q4;
            #pragma unroll
            for (int d = 0; d < KW; d++) {
                float4 tv = *(const float4*)(base + d * HW);
                float k = sKer[d];
                a.x += tv.x * k; a.y += tv.y * k;
                a.z += tv.z * k; a.w += tv.w * k;
            }
            int px = 4 * q4;
            sSp[c * 96 + px + 0] = a.x * sGix[px + 0];
            sSp[c * 96 + px + 1] = a.y * sGix[px + 1];
            sSp[c * 96 + px + 2] = a.z * sGix[px + 2];
            sSp[c * 96 + px + 3] = a.w * sGix[px + 3];
        }
        __syncthreads();

        // ---- S3: q = u - cvec - sp - bl; exp -------------------------------
        if (tid < 672) {
            #pragma unroll
            for (int j = 0; j < 3; j++) {
                int idx = tid + j * 672;
                int o = idx / 96, px = idx % 96;
                float bl = (sBlP[idx] + sBlP[2016 + idx] + sBlP[4032 + idx]) * sNbI[px];
                float q = sU[idx] - sCv[o] - sSp[idx] - bl;
                sQ[idx] = __expf(q);
            }
        }
        __syncthreads();

        // ---- S4: inv-sum (+ final output) ----------------------------------
        if (tid < HW) {
            int px = tid;
            float ss = 0.0f;
            #pragma unroll
            for (int o = 0; o < NC; o++) ss += sQ[o * 96 + px];
            float inv = __fdividef(1.0f, ss);
            sIv[px] = inv;
            if (it == 4) {
                #pragma unroll
                for (int o = 0; o < NC; o++)
                    out[o * NPIX + y * HW + px] = sQ[o * 96 + px] * inv;
            }
        }
        if (it == 4) break;
        __syncthreads();

        // ---- S5: mix t1, t2 ------------------------------------------------
        if (tid < 336) {
            int og = tid / 48, pp = tid % 48;
            int o0 = og * 3;
            ull t1a[3] = {0, 0, 0}, t2a[3] = {0, 0, 0};
            for (int c = 0; c < NC; c++) {
                ull sv = *(const ull*)(sQ + c * 96 + 2 * pp);
                #pragma unroll
                for (int k = 0; k < 3; k++) {
                    fma2(t1a[k], sv, sW1D[(o0 + k) * NC + c]);
                    fma2(t2a[k], sv, sW2D[(o0 + k) * NC + c]);
                }
            }
            float i0 = sIv[2 * pp], i1 = sIv[2 * pp + 1];
            #pragma unroll
            for (int k = 0; k < 3; k++) {
                sT1[(o0 + k) * 128 + 16 + 2 * pp]     = lo2(t1a[k]) * i0;
                sT1[(o0 + k) * 128 + 16 + 2 * pp + 1] = hi2(t1a[k]) * i1;
                sT2[(o0 + k) * 96 + 2 * pp]           = lo2(t2a[k]) * i0;
                sT2[(o0 + k) * 96 + 2 * pp + 1]       = hi2(t2a[k]) * i1;
            }
        }
        __syncthreads();

        // ---- S6: spX(t1) | moments(t2) -------------------------------------
        if (tid < 504) {
            int c = tid / 24, q4 = tid % 24;
            float w[28];
            const float* base = sT1 + c * 128 + 4 + 4 * q4;
            #pragma unroll
            for (int i = 0; i < 7; i++) *(float4*)(w + 4 * i) = *(const float4*)(base + 4 * i);
            float a0 = 0.f, a1 = 0.f, a2 = 0.f, a3 = 0.f;
            #pragma unroll
            for (int d = 0; d < KW; d++) {
                float k = sKer[d];
                a0 += k * w[d]; a1 += k * w[d + 1]; a2 += k * w[d + 2]; a3 += k * w[d + 3];
            }
            *(float4*)(g_tmpP + (c * TROWS + KR + y) * HW + 4 * q4) = make_float4(a0, a1, a2, a3);
        } else if (tid >= 512 && tid < 708) {
            int u2 = tid - 512;
            int quarter = u2 / 49, r2 = u2 % 49;
            int cg = r2 / 7, rg = r2 % 7;
            int r0 = rg * 3, c0 = cg * 3;
            ull acc[9];
            #pragma unroll
            for (int k = 0; k < 9; k++) acc[k] = 0ull;
            int p0 = quarter * 12;
            for (int p = p0; p < p0 + 12; p++) {
                ull ph0 = *(const ull*)(sPhi + (r0 + 0) * PHS + 2 * p);
                ull ph1 = *(const ull*)(sPhi + (r0 + 1) * PHS + 2 * p);
                ull ph2 = *(const ull*)(sPhi + (r0 + 2) * PHS + 2 * p);
                #pragma unroll
                for (int j = 0; j < 3; j++) {
                    ull sv = *(const ull*)(sT2 + (c0 + j) * 96 + 2 * p);
                    fma2(acc[j * 3 + 0], ph0, sv);
                    fma2(acc[j * 3 + 1], ph1, sv);
                    fma2(acc[j * 3 + 2], ph2, sv);
                }
            }
            #pragma unroll
            for (int j = 0; j < 3; j++)
                #pragma unroll
                for (int i = 0; i < 3; i++)
                    sMomP[quarter * NMOM + (c0 + j) * RD + r0 + i] =
                        lo2(acc[j * 3 + i]) + hi2(acc[j * 3 + i]);
        }
        __syncthreads();
        // ---- S6b: reduce -> mom[wrb] ---------------------------------------
        if (tid < NMOM) {
            float v = sMomP[tid] + sMomP[NMOM + tid]
                    + sMomP[2 * NMOM + tid] + sMomP[3 * NMOM + tid];
            atomicAdd(&g_mom[wrb * NMOM + tid], v);
        }
        gsync();                             // barriers #2..#5
    }
}

// ------------------------------ launch -------------------------------------
extern "C" void kernel_launch(void* const* d_in, const int* in_sizes, int n_in,
                              void* d_out, int out_size) {
    const float* image  = (const float*)d_in[0];
    const float* net_w  = (const float*)d_in[1];
    const float* net_b  = (const float*)d_in[2];
    const float* sp_w   = (const float*)d_in[3];
    const float* sp_b   = (const float*)d_in[4];
    const float* bl_w   = (const float*)d_in[5];
    const float* bl_b   = (const float*)d_in[6];
    const float* comp_w = (const float*)d_in[7];
    const float* comp_b = (const float*)d_in[8];
    float* out = (float*)d_out;

    static int smem_set = 0;
    if (!smem_set) {
        cudaFuncSetAttribute(crf_all, cudaFuncAttributeMaxDynamicSharedMemorySize,
                             SMEM_BYTES);
        smem_set = 1;
    }
    crf_all<<<GRID, TPB, SMEM_BYTES>>>(image, net_w, net_b, sp_w, sp_b,
                                       bl_w, bl_b, comp_w, comp_b, out);
}